// round 8
// baseline (speedup 1.0000x reference)
#include <cuda_runtime.h>
#include <cuda_fp16.h>
#include <cstdint>

// ---------------- problem constants ----------------
#define NIMG 32
#define CI   128
#define HH   56
#define WW   56
#define CO   256
#define HP   58
#define WP   58
#define PIX  (HH*WW)          // 3136
#define MTOT (NIMG*PIX)       // 100352

// fp16 scratch (static device globals: allowed)
__device__ __align__(1024) __half g_xh[(size_t)NIMG*HP*WP*CI];  // NHWC + halo
__device__ __align__(1024) __half g_wh[(size_t)9*CO*CI];        // [kc][co][ci]

// ---------------- prep kernels ----------------
__global__ void fill_halo() {
    int n = blockIdx.x, hp = blockIdx.y;
    uint4 z = make_uint4(0, 0, 0, 0);
    __half* base = g_xh + ((size_t)(n * HP + hp)) * WP * CI;
    if (hp == 0 || hp == HP - 1) {
        for (int i = threadIdx.x; i < WP * CI / 8; i += blockDim.x)
            reinterpret_cast<uint4*>(base)[i] = z;
    } else {
        if (threadIdx.x < 16)
            reinterpret_cast<uint4*>(base)[threadIdx.x] = z;
        else if (threadIdx.x < 32)
            reinterpret_cast<uint4*>(base + (size_t)(WP - 1) * CI)[threadIdx.x - 16] = z;
    }
}

__global__ void convert_w(const float* __restrict__ W) {
    int i = blockIdx.x * 256 + threadIdx.x;
    if (i >= CO * CI * 9) return;
    // W layout: [co][ci][kh][kw]
    int kw = i % 3; int t = i / 3;
    int kh = t % 3; t /= 3;
    int ci = t % CI; int co = t / CI;
    float v = rintf(W[i] * 128.0f);              // exact integer, exact in fp16
    g_wh[(size_t)((kh * 3 + kw) * CO + co) * CI + ci] = __float2half_rn(v);
}

// NCHW fp32 -> NHWC(+halo) fp16
__global__ void transpose_x(const float* __restrict__ x) {
    __shared__ __half s[CI * 58];
    int h = blockIdx.x, n = blockIdx.y;
    const float* xp = x + ((size_t)n * CI) * PIX + h * WW;
    for (int id = threadIdx.x; id < CI * WW; id += 256) {
        int ci = id / WW, w = id % WW;
        s[ci * 58 + w] = __float2half_rn(xp[(size_t)ci * PIX + w]);
    }
    __syncthreads();
    __half* dst = g_xh + ((size_t)((n * HP + h + 1) * WP + 1)) * CI;
    for (int id = threadIdx.x; id < WW * CI; id += 256) {
        int w = id / CI, ci = id % CI;
        dst[(size_t)w * CI + ci] = s[ci * 58 + w];
    }
}

// ---------------- GEMM (HMMA, 2 CTAs/SM, per-warp k16 rotation) ----------------
// CTA: 128 pix x 128 co, 256 threads. K: 18 chunks of 64 ci (9 taps x 2 halves).
// 8 warps 4m x 2n, warp tile 32x64, mma m16n8k16 f32.f16. 2 CTAs resident/SM.
// Each warp rotates its k16 order so LDSM/HMMA phases interleave across warps.

#define ROWB    144                 // 128B data + 16B pad
#define BOFF    (128 * ROWB)        // B tile offset within a stage
#define STAGE   (256 * ROWB)        // 36864
#define NSTAGE  3
#define NT      18
#define HDR     512
#define SMEM_DYN (HDR + NSTAGE * STAGE)   // 111104 -> 2 CTAs/SM

__device__ __forceinline__ void ldsm_x4(uint32_t addr, uint32_t& r0, uint32_t& r1,
                                        uint32_t& r2, uint32_t& r3) {
    asm volatile("ldmatrix.sync.aligned.m8n8.x4.shared.b16 {%0,%1,%2,%3}, [%4];\n"
                 : "=r"(r0), "=r"(r1), "=r"(r2), "=r"(r3) : "r"(addr));
}

__global__ void __launch_bounds__(256, 2) qconv_gemm(const float* __restrict__ bias,
                                                     float* __restrict__ out) {
    extern __shared__ char smem[];
    float* bq = reinterpret_cast<float*>(smem);
    const uint32_t sb = (uint32_t)__cvta_generic_to_shared(smem);

    const int tid = threadIdx.x;
    const int m_base  = blockIdx.x * 128;
    const int co_base = blockIdx.y * 128;

    if (tid < 128) bq[tid] = rintf(bias[co_base + tid] * 128.0f);

    // compressed cp.async endpoint state: piece i: row = (tid>>3) + 32*i
    const char* xh = reinterpret_cast<const char*>(g_xh);
    const char* wh = reinterpret_cast<const char*>(g_wh);
    const int row0 = tid >> 3, ch0 = (tid & 7) * 16;
    const char* aSrc[4];
    #pragma unroll
    for (int i = 0; i < 4; i++) {
        int p = m_base + row0 + 32 * i;
        int ni = p / PIX; int rem = p - ni * PIX;
        int h = rem / WW; int w = rem - h * WW;
        aSrc[i] = xh + ((size_t)((ni * HP + h) * WP + w)) * 256 + ch0;  // window top-left
    }
    const char* bSrc0 = wh + (size_t)(co_base + row0) * 256 + ch0;
    const uint32_t aDst0 = sb + HDR + row0 * ROWB + ch0;
    const uint32_t bDst0 = sb + HDR + BOFF + row0 * ROWB + ch0;

    // issue one K-chunk's loads into a stage slot; chunk t: kc = t>>1, half = t&1
    auto issue = [&](int t, int slot) {
        int kc = t >> 1, hf = t & 1;
        int kh = kc / 3, kw = kc - kh * 3;
        uint32_t aoff = (uint32_t)((kh * WP + kw) * 256 + hf * 128);
        uint32_t boff = (uint32_t)(kc * (CO * 256) + hf * 128);
        uint32_t so = slot * STAGE;
        #pragma unroll
        for (int i = 0; i < 4; i++)
            asm volatile("cp.async.cg.shared.global [%0], [%1], 16;\n"
                         :: "r"(aDst0 + so + i * (32 * ROWB)), "l"(aSrc[i] + aoff));
        #pragma unroll
        for (int i = 0; i < 4; i++)
            asm volatile("cp.async.cg.shared.global [%0], [%1], 16;\n"
                         :: "r"(bDst0 + so + i * (32 * ROWB)), "l"(bSrc0 + boff + (size_t)i * 8192));
        asm volatile("cp.async.commit_group;\n" ::: "memory");
    };

    const int warp = tid >> 5, lane = tid & 31;
    const int warp_m = (warp & 3) * 32;
    const int warp_n = (warp >> 2) * 64;
    const uint32_t krot = (uint32_t)(warp & 3) * 32;   // per-warp k16 phase offset (bytes)

    float acc[2][8][4];
    #pragma unroll
    for (int i = 0; i < 2; i++)
        #pragma unroll
        for (int j = 0; j < 8; j++)
            #pragma unroll
            for (int k = 0; k < 4; k++) acc[i][j][k] = 0.0f;

    const uint32_t aoff0 = (uint32_t)((warp_m + (lane & 15)) * ROWB + (lane >> 4) * 16);
    const uint32_t boff0 = (uint32_t)(BOFF + (warp_n + (lane & 7) + ((lane >> 4) << 3)) * ROWB
                                      + ((lane >> 3) & 1) * 16);

    // prologue: fill 2 of 3 stages
    issue(0, 0); issue(1, 1);

    #pragma unroll 1
    for (int t = 0; t < NT; t++) {
        asm volatile("cp.async.wait_group 1;\n" ::: "memory");
        __syncthreads();
        int tn = t + 2;
        if (tn < NT) issue(tn, tn - (tn / 3) * 3);
        else asm volatile("cp.async.commit_group;\n" ::: "memory");  // keep group count

        uint32_t sA = sb + HDR + (t - (t / 3) * 3) * STAGE;
        #pragma unroll
        for (int kk = 0; kk < 4; kk++) {
            // rotated k16: each warp starts at a different phase; wraps mod 4 (128B)
            uint32_t koff = (krot + (uint32_t)kk * 32) & 127;
            uint32_t a[2][4];
            #pragma unroll
            for (int mf = 0; mf < 2; mf++)
                ldsm_x4(sA + aoff0 + mf * (16 * ROWB) + koff,
                        a[mf][0], a[mf][1], a[mf][2], a[mf][3]);
            uint32_t b[8][2];
            #pragma unroll
            for (int j = 0; j < 4; j++) {
                uint32_t r0, r1, r2, r3;
                ldsm_x4(sA + boff0 + j * (16 * ROWB) + koff, r0, r1, r2, r3);
                b[2*j][0] = r0; b[2*j][1] = r1; b[2*j+1][0] = r2; b[2*j+1][1] = r3;
            }
            #pragma unroll
            for (int mf = 0; mf < 2; mf++)
                #pragma unroll
                for (int nf = 0; nf < 8; nf++) {
                    asm volatile(
                        "mma.sync.aligned.m16n8k16.row.col.f32.f16.f16.f32 "
                        "{%0,%1,%2,%3}, {%4,%5,%6,%7}, {%8,%9}, {%0,%1,%2,%3};\n"
                        : "+f"(acc[mf][nf][0]), "+f"(acc[mf][nf][1]),
                          "+f"(acc[mf][nf][2]), "+f"(acc[mf][nf][3])
                        : "r"(a[mf][0]), "r"(a[mf][1]), "r"(a[mf][2]), "r"(a[mf][3]),
                          "r"(b[nf][0]), "r"(b[nf][1]));
                }
        }
    }

    // epilogue: out[n][co][h][w] = acc/128 + round(b*128)
    const float inv = 0.0078125f;
    #pragma unroll
    for (int mf = 0; mf < 2; mf++) {
        #pragma unroll
        for (int hsel = 0; hsel < 2; hsel++) {
            int m = warp_m + mf * 16 + (lane >> 2) + hsel * 8;
            int p = m_base + m;
            int ni = p / PIX; int rem = p - ni * PIX;
            int h = rem / WW; int w = rem - h * WW;
            float* op = out + (size_t)ni * CO * PIX + h * WW + w;
            #pragma unroll
            for (int nf = 0; nf < 8; nf++) {
                int col = warp_n + nf * 8 + 2 * (lane & 3);
                int co  = co_base + col;
                op[(size_t)co * PIX]       = acc[mf][nf][hsel*2 + 0] * inv + bq[col];
                op[(size_t)(co + 1) * PIX] = acc[mf][nf][hsel*2 + 1] * inv + bq[col + 1];
            }
        }
    }
}

// ---------------- launch ----------------
extern "C" void kernel_launch(void* const* d_in, const int* in_sizes, int n_in,
                              void* d_out, int out_size) {
    const float* x = (const float*)d_in[0];
    const float* W = (const float*)d_in[1];
    const float* b = (const float*)d_in[2];
    float* out = (float*)d_out;

    fill_halo<<<dim3(NIMG, HP), 128>>>();
    convert_w<<<(CO * CI * 9 + 255) / 256, 256>>>(W);
    transpose_x<<<dim3(HH, NIMG), 256>>>(x);

    cudaFuncSetAttribute(qconv_gemm, cudaFuncAttributeMaxDynamicSharedMemorySize, SMEM_DYN);
    qconv_gemm<<<dim3(MTOT / 128, CO / 128), 256, SMEM_DYN>>>(b, out);
}

// round 9
// speedup vs baseline: 1.4878x; 1.4878x over previous
#include <cuda_runtime.h>
#include <cuda_fp16.h>
#include <cstdint>

// ---------------- problem constants ----------------
#define NIMG 32
#define CI   128
#define HH   56
#define WW   56
#define CO   256
#define HP   58
#define WP   58
#define PIX  (HH*WW)          // 3136
#define MTOT (NIMG*PIX)       // 100352

// fp16 scratch (static device globals: allowed)
__device__ __align__(1024) __half g_xh[(size_t)NIMG*HP*WP*CI];  // NHWC + halo
__device__ __align__(1024) __half g_wh[(size_t)9*CO*CI];        // [kc][co][ci]

// ---------------- prep kernels ----------------
__global__ void fill_halo() {
    int n = blockIdx.x, hp = blockIdx.y;
    uint4 z = make_uint4(0, 0, 0, 0);
    __half* base = g_xh + ((size_t)(n * HP + hp)) * WP * CI;
    if (hp == 0 || hp == HP - 1) {
        for (int i = threadIdx.x; i < WP * CI / 8; i += blockDim.x)
            reinterpret_cast<uint4*>(base)[i] = z;
    } else {
        if (threadIdx.x < 16)
            reinterpret_cast<uint4*>(base)[threadIdx.x] = z;
        else if (threadIdx.x < 32)
            reinterpret_cast<uint4*>(base + (size_t)(WP - 1) * CI)[threadIdx.x - 16] = z;
    }
}

__global__ void convert_w(const float* __restrict__ W) {
    int i = blockIdx.x * 256 + threadIdx.x;
    if (i >= CO * CI * 9) return;
    // W layout: [co][ci][kh][kw]
    int kw = i % 3; int t = i / 3;
    int kh = t % 3; t /= 3;
    int ci = t % CI; int co = t / CI;
    float v = rintf(W[i] * 128.0f);              // exact integer, exact in fp16
    g_wh[(size_t)((kh * 3 + kw) * CO + co) * CI + ci] = __float2half_rn(v);
}

// NCHW fp32 -> NHWC(+halo) fp16
__global__ void transpose_x(const float* __restrict__ x) {
    __shared__ __half s[CI * 58];
    int h = blockIdx.x, n = blockIdx.y;
    const float* xp = x + ((size_t)n * CI) * PIX + h * WW;
    for (int id = threadIdx.x; id < CI * WW; id += 256) {
        int ci = id / WW, w = id % WW;
        s[ci * 58 + w] = __float2half_rn(xp[(size_t)ci * PIX + w]);
    }
    __syncthreads();
    __half* dst = g_xh + ((size_t)((n * HP + h + 1) * WP + 1)) * CI;
    for (int id = threadIdx.x; id < WW * CI; id += 256) {
        int w = id / CI, ci = id % CI;
        dst[(size_t)w * CI + ci] = s[ci * 58 + w];
    }
}

// ---------------- GEMM (HMMA, 4 CTAs/SM) ----------------
// CTA: 64 pix x 128 co, 128 threads, 4 warps (2m x 2n), warp tile 32x64.
// K: 18 chunks of 64 ci (9 taps x 2 halves). 2-stage cp.async double buffer.
// 4 independent CTAs resident per SM -> 4 desynchronized barrier domains.

#define ROWB    144                 // 128B data + 16B pad
#define BOFF    (64 * ROWB)         // B tile offset within a stage (A = 64 rows)
#define STAGE   (192 * ROWB)        // 27648 (64 A-rows + 128 B-rows)
#define NSTAGE  2
#define NT      18
#define HDR     512
#define SMEM_DYN (HDR + NSTAGE * STAGE)   // 55808 -> 4 CTAs/SM

__device__ __forceinline__ void ldsm_x4(uint32_t addr, uint32_t& r0, uint32_t& r1,
                                        uint32_t& r2, uint32_t& r3) {
    asm volatile("ldmatrix.sync.aligned.m8n8.x4.shared.b16 {%0,%1,%2,%3}, [%4];\n"
                 : "=r"(r0), "=r"(r1), "=r"(r2), "=r"(r3) : "r"(addr));
}

__global__ void __launch_bounds__(128, 4) qconv_gemm(const float* __restrict__ bias,
                                                     float* __restrict__ out) {
    extern __shared__ char smem[];
    float* bq = reinterpret_cast<float*>(smem);
    const uint32_t sb = (uint32_t)__cvta_generic_to_shared(smem);

    const int tid = threadIdx.x;
    const int m_base  = blockIdx.x * 64;
    const int co_base = blockIdx.y * 128;

    bq[tid] = rintf(bias[co_base + tid] * 128.0f);

    // cp.async endpoints: row0 = tid>>3 in [0,16), 16-row strides per piece
    const char* xh = reinterpret_cast<const char*>(g_xh);
    const char* wh = reinterpret_cast<const char*>(g_wh);
    const int row0 = tid >> 3, ch0 = (tid & 7) * 16;
    const char* aSrc[4];
    #pragma unroll
    for (int i = 0; i < 4; i++) {                // A rows row0 + 16*i in [0,64)
        int p = m_base + row0 + 16 * i;
        int ni = p / PIX; int rem = p - ni * PIX;
        int h = rem / WW; int w = rem - h * WW;
        aSrc[i] = xh + ((size_t)((ni * HP + h) * WP + w)) * 256 + ch0;  // window top-left
    }
    const char* bSrc0 = wh + (size_t)(co_base + row0) * 256 + ch0;
    const uint32_t aDst0 = sb + HDR + row0 * ROWB + ch0;
    const uint32_t bDst0 = sb + HDR + BOFF + row0 * ROWB + ch0;

    // issue one K-chunk's loads into a stage slot; chunk t: kc = t>>1, half = t&1
    auto issue = [&](int t, int slot) {
        int kc = t >> 1, hf = t & 1;
        int kh = kc / 3, kw = kc - kh * 3;
        uint32_t aoff = (uint32_t)((kh * WP + kw) * 256 + hf * 128);
        uint32_t boff = (uint32_t)(kc * (CO * 256) + hf * 128);
        uint32_t so = slot * STAGE;
        #pragma unroll
        for (int i = 0; i < 4; i++)
            asm volatile("cp.async.cg.shared.global [%0], [%1], 16;\n"
                         :: "r"(aDst0 + so + i * (16 * ROWB)), "l"(aSrc[i] + aoff));
        #pragma unroll
        for (int i = 0; i < 8; i++)              // B rows row0 + 16*i in [0,128)
            asm volatile("cp.async.cg.shared.global [%0], [%1], 16;\n"
                         :: "r"(bDst0 + so + i * (16 * ROWB)), "l"(bSrc0 + boff + (size_t)i * 4096));
        asm volatile("cp.async.commit_group;\n" ::: "memory");
    };

    const int warp = tid >> 5, lane = tid & 31;
    const int warp_m = (warp & 1) * 32;
    const int warp_n = (warp >> 1) * 64;

    float acc[2][8][4];
    #pragma unroll
    for (int i = 0; i < 2; i++)
        #pragma unroll
        for (int j = 0; j < 8; j++)
            #pragma unroll
            for (int k = 0; k < 4; k++) acc[i][j][k] = 0.0f;

    const uint32_t aoff0 = (uint32_t)((warp_m + (lane & 15)) * ROWB + (lane >> 4) * 16);
    const uint32_t boff0 = (uint32_t)(BOFF + (warp_n + (lane & 7) + ((lane >> 4) << 3)) * ROWB
                                      + ((lane >> 3) & 1) * 16);

    // prologue: fill both stages
    issue(0, 0); issue(1, 1);

    #pragma unroll 1
    for (int t = 0; t < NT; t++) {
        asm volatile("cp.async.wait_group 1;\n" ::: "memory");
        __syncthreads();

        uint32_t sA = sb + HDR + (t & 1) * STAGE;
        #pragma unroll
        for (int k16 = 0; k16 < 4; k16++) {
            uint32_t a[2][4];
            #pragma unroll
            for (int mf = 0; mf < 2; mf++)
                ldsm_x4(sA + aoff0 + mf * (16 * ROWB) + k16 * 32,
                        a[mf][0], a[mf][1], a[mf][2], a[mf][3]);
            uint32_t b[8][2];
            #pragma unroll
            for (int j = 0; j < 4; j++) {
                uint32_t r0, r1, r2, r3;
                ldsm_x4(sA + boff0 + j * (16 * ROWB) + k16 * 32, r0, r1, r2, r3);
                b[2*j][0] = r0; b[2*j][1] = r1; b[2*j+1][0] = r2; b[2*j+1][1] = r3;
            }
            #pragma unroll
            for (int mf = 0; mf < 2; mf++)
                #pragma unroll
                for (int nf = 0; nf < 8; nf++) {
                    asm volatile(
                        "mma.sync.aligned.m16n8k16.row.col.f32.f16.f16.f32 "
                        "{%0,%1,%2,%3}, {%4,%5,%6,%7}, {%8,%9}, {%0,%1,%2,%3};\n"
                        : "+f"(acc[mf][nf][0]), "+f"(acc[mf][nf][1]),
                          "+f"(acc[mf][nf][2]), "+f"(acc[mf][nf][3])
                        : "r"(a[mf][0]), "r"(a[mf][1]), "r"(a[mf][2]), "r"(a[mf][3]),
                          "r"(b[nf][0]), "r"(b[nf][1]));
                }
        }

        __syncthreads();                 // all warps done reading slot before refill
        int tn = t + 2;
        if (tn < NT) issue(tn, tn & 1);
        else asm volatile("cp.async.commit_group;\n" ::: "memory");  // keep group count
    }

    // epilogue: out[n][co][h][w] = acc/128 + round(b*128)
    const float inv = 0.0078125f;
    #pragma unroll
    for (int mf = 0; mf < 2; mf++) {
        #pragma unroll
        for (int hsel = 0; hsel < 2; hsel++) {
            int m = warp_m + mf * 16 + (lane >> 2) + hsel * 8;
            int p = m_base + m;
            int ni = p / PIX; int rem = p - ni * PIX;
            int h = rem / WW; int w = rem - h * WW;
            float* op = out + (size_t)ni * CO * PIX + h * WW + w;
            #pragma unroll
            for (int nf = 0; nf < 8; nf++) {
                int col = warp_n + nf * 8 + 2 * (lane & 3);
                int co  = co_base + col;
                op[(size_t)co * PIX]       = acc[mf][nf][hsel*2 + 0] * inv + bq[col];
                op[(size_t)(co + 1) * PIX] = acc[mf][nf][hsel*2 + 1] * inv + bq[col + 1];
            }
        }
    }
}

// ---------------- launch ----------------
extern "C" void kernel_launch(void* const* d_in, const int* in_sizes, int n_in,
                              void* d_out, int out_size) {
    const float* x = (const float*)d_in[0];
    const float* W = (const float*)d_in[1];
    const float* b = (const float*)d_in[2];
    float* out = (float*)d_out;

    fill_halo<<<dim3(NIMG, HP), 128>>>();
    convert_w<<<(CO * CI * 9 + 255) / 256, 256>>>(W);
    transpose_x<<<dim3(HH, NIMG), 256>>>(x);

    cudaFuncSetAttribute(qconv_gemm, cudaFuncAttributeMaxDynamicSharedMemorySize, SMEM_DYN);
    qconv_gemm<<<dim3(MTOT / 64, CO / 128), 128, SMEM_DYN>>>(b, out);
}

// round 10
// speedup vs baseline: 1.5480x; 1.0404x over previous
#include <cuda_runtime.h>
#include <cuda_fp16.h>
#include <cstdint>

// ---------------- problem constants ----------------
#define NIMG 32
#define CI   128
#define HH   56
#define WW   56
#define CO   256
#define HP   58
#define WP   58
#define PIX  (HH*WW)          // 3136
#define MTOT (NIMG*PIX)       // 100352

// fp16 scratch (static device globals: allowed)
__device__ __align__(1024) __half g_xh[(size_t)NIMG*HP*WP*CI];  // NHWC + halo
__device__ __align__(1024) __half g_wh[(size_t)9*CO*CI];        // [kc][co][ci]

// ---------------- fused prep kernel ----------------
// blocks [0, 1792): transpose one (n,h) row  (h = bid%56, n = bid/56)
// blocks [1792, 1824): zero halo for image n = bid-1792
// blocks [1824, 1860): convert 8192 weight elements each
#define TBLK 1792
#define HBLK 32
#define WBLK 36

__global__ void __launch_bounds__(256) prep(const float* __restrict__ x,
                                            const float* __restrict__ W) {
    const int bid = blockIdx.x, tid = threadIdx.x;

    if (bid < TBLK) {
        // NCHW fp32 -> NHWC fp16 for one (n, h) row, via smem transpose
        __shared__ __half s[CI * 58];
        int h = bid % 56, n = bid / 56;
        const float* xp = x + ((size_t)n * CI) * PIX + h * WW;
        for (int id = tid; id < CI * WW; id += 256) {
            int ci = id / WW, w = id % WW;
            s[ci * 58 + w] = __float2half_rn(xp[(size_t)ci * PIX + w]);
        }
        __syncthreads();
        __half2* dst = reinterpret_cast<__half2*>(
            g_xh + ((size_t)((n * HP + h + 1) * WP + 1)) * CI);
        for (int id = tid; id < WW * (CI / 2); id += 256) {
            int w = id >> 6, c2 = id & 63;       // CI/2 = 64
            dst[w * (CI / 2) + c2] =
                __halves2half2(s[(2 * c2) * 58 + w], s[(2 * c2 + 1) * 58 + w]);
        }
    } else if (bid < TBLK + HBLK) {
        // zero halo of image n: rows hp=0,57 fully; wp=0,57 edges of rows 1..56
        int n = bid - TBLK;
        uint4 z = make_uint4(0, 0, 0, 0);
        __half* b0 = g_xh + (size_t)(n * HP + 0)  * WP * CI;
        __half* b1 = g_xh + (size_t)(n * HP + 57) * WP * CI;
        for (int i = tid; i < WP * CI / 8; i += 256) {
            reinterpret_cast<uint4*>(b0)[i] = z;
            reinterpret_cast<uint4*>(b1)[i] = z;
        }
        for (int i = tid; i < 56 * 2 * 16; i += 256) {  // 56 rows x 2 edges x 16 uint4
            int r = i >> 5; int e = (i >> 4) & 1; int q = i & 15;
            __half* eb = g_xh + (size_t)((n * HP + 1 + r) * WP + e * 57) * CI;
            reinterpret_cast<uint4*>(eb)[q] = z;
        }
    } else {
        // weights: round(W*128) -> fp16, layout [kc][co][ci]
        int i0 = (bid - TBLK - HBLK) * 8192;
        for (int k = tid; k < 8192; k += 256) {
            int i = i0 + k;
            int kw = i % 3; int t = i / 3;
            int kh = t % 3; t /= 3;
            int ci = t % CI; int co = t / CI;
            float v = rintf(W[i] * 128.0f);      // exact integer, exact in fp16
            g_wh[(size_t)((kh * 3 + kw) * CO + co) * CI + ci] = __float2half_rn(v);
        }
    }
}

// ---------------- GEMM (HMMA, 2 CTAs/SM) — round-6 champion, unchanged ----------
// CTA: 128 pix x 128 co, 256 threads. K: 18 chunks of 64 ci (9 taps x 2 halves).
// 8 warps 4m x 2n, warp tile 32x64, mma m16n8k16 f32.f16. 2 CTAs resident/SM.

#define ROWB    144                 // 128B data + 16B pad
#define BOFF    (128 * ROWB)        // B tile offset within a stage
#define STAGE   (256 * ROWB)        // 36864
#define NSTAGE  3
#define NT      18
#define HDR     512
#define SMEM_DYN (HDR + NSTAGE * STAGE)   // 111104 -> 2 CTAs/SM

__device__ __forceinline__ void ldsm_x4(uint32_t addr, uint32_t& r0, uint32_t& r1,
                                        uint32_t& r2, uint32_t& r3) {
    asm volatile("ldmatrix.sync.aligned.m8n8.x4.shared.b16 {%0,%1,%2,%3}, [%4];\n"
                 : "=r"(r0), "=r"(r1), "=r"(r2), "=r"(r3) : "r"(addr));
}

__global__ void __launch_bounds__(256, 2) qconv_gemm(const float* __restrict__ bias,
                                                     float* __restrict__ out) {
    extern __shared__ char smem[];
    float* bq = reinterpret_cast<float*>(smem);
    const uint32_t sb = (uint32_t)__cvta_generic_to_shared(smem);

    const int tid = threadIdx.x;
    const int m_base  = blockIdx.x * 128;
    const int co_base = blockIdx.y * 128;

    if (tid < 128) bq[tid] = rintf(bias[co_base + tid] * 128.0f);

    // compressed cp.async endpoint state: piece i: row = (tid>>3) + 32*i
    const char* xh = reinterpret_cast<const char*>(g_xh);
    const char* wh = reinterpret_cast<const char*>(g_wh);
    const int row0 = tid >> 3, ch0 = (tid & 7) * 16;
    const char* aSrc[4];
    #pragma unroll
    for (int i = 0; i < 4; i++) {
        int p = m_base + row0 + 32 * i;
        int ni = p / PIX; int rem = p - ni * PIX;
        int h = rem / WW; int w = rem - h * WW;
        aSrc[i] = xh + ((size_t)((ni * HP + h) * WP + w)) * 256 + ch0;  // window top-left
    }
    const char* bSrc0 = wh + (size_t)(co_base + row0) * 256 + ch0;
    const uint32_t aDst0 = sb + HDR + row0 * ROWB + ch0;
    const uint32_t bDst0 = sb + HDR + BOFF + row0 * ROWB + ch0;

    // issue one K-chunk's loads into a stage slot; chunk t: kc = t>>1, half = t&1
    auto issue = [&](int t, int slot) {
        int kc = t >> 1, hf = t & 1;
        int kh = kc / 3, kw = kc - kh * 3;
        uint32_t aoff = (uint32_t)((kh * WP + kw) * 256 + hf * 128);
        uint32_t boff = (uint32_t)(kc * (CO * 256) + hf * 128);
        uint32_t so = slot * STAGE;
        #pragma unroll
        for (int i = 0; i < 4; i++)
            asm volatile("cp.async.cg.shared.global [%0], [%1], 16;\n"
                         :: "r"(aDst0 + so + i * (32 * ROWB)), "l"(aSrc[i] + aoff));
        #pragma unroll
        for (int i = 0; i < 4; i++)
            asm volatile("cp.async.cg.shared.global [%0], [%1], 16;\n"
                         :: "r"(bDst0 + so + i * (32 * ROWB)), "l"(bSrc0 + boff + (size_t)i * 8192));
        asm volatile("cp.async.commit_group;\n" ::: "memory");
    };

    const int warp = tid >> 5, lane = tid & 31;
    const int warp_m = (warp & 3) * 32;
    const int warp_n = (warp >> 2) * 64;

    float acc[2][8][4];
    #pragma unroll
    for (int i = 0; i < 2; i++)
        #pragma unroll
        for (int j = 0; j < 8; j++)
            #pragma unroll
            for (int k = 0; k < 4; k++) acc[i][j][k] = 0.0f;

    const uint32_t aoff0 = (uint32_t)((warp_m + (lane & 15)) * ROWB + (lane >> 4) * 16);
    const uint32_t boff0 = (uint32_t)(BOFF + (warp_n + (lane & 7) + ((lane >> 4) << 3)) * ROWB
                                      + ((lane >> 3) & 1) * 16);

    // prologue: fill 2 of 3 stages
    issue(0, 0); issue(1, 1);

    #pragma unroll 1
    for (int t = 0; t < NT; t++) {
        asm volatile("cp.async.wait_group 1;\n" ::: "memory");
        __syncthreads();
        int tn = t + 2;
        if (tn < NT) issue(tn, tn - (tn / 3) * 3);
        else asm volatile("cp.async.commit_group;\n" ::: "memory");  // keep group count

        uint32_t sA = sb + HDR + (t - (t / 3) * 3) * STAGE;
        #pragma unroll
        for (int k16 = 0; k16 < 4; k16++) {
            uint32_t a[2][4];
            #pragma unroll
            for (int mf = 0; mf < 2; mf++)
                ldsm_x4(sA + aoff0 + mf * (16 * ROWB) + k16 * 32,
                        a[mf][0], a[mf][1], a[mf][2], a[mf][3]);
            uint32_t b[8][2];
            #pragma unroll
            for (int j = 0; j < 4; j++) {
                uint32_t r0, r1, r2, r3;
                ldsm_x4(sA + boff0 + j * (16 * ROWB) + k16 * 32, r0, r1, r2, r3);
                b[2*j][0] = r0; b[2*j][1] = r1; b[2*j+1][0] = r2; b[2*j+1][1] = r3;
            }
            #pragma unroll
            for (int mf = 0; mf < 2; mf++)
                #pragma unroll
                for (int nf = 0; nf < 8; nf++) {
                    asm volatile(
                        "mma.sync.aligned.m16n8k16.row.col.f32.f16.f16.f32 "
                        "{%0,%1,%2,%3}, {%4,%5,%6,%7}, {%8,%9}, {%0,%1,%2,%3};\n"
                        : "+f"(acc[mf][nf][0]), "+f"(acc[mf][nf][1]),
                          "+f"(acc[mf][nf][2]), "+f"(acc[mf][nf][3])
                        : "r"(a[mf][0]), "r"(a[mf][1]), "r"(a[mf][2]), "r"(a[mf][3]),
                          "r"(b[nf][0]), "r"(b[nf][1]));
                }
        }
    }

    // epilogue: out[n][co][h][w] = acc/128 + round(b*128)
    const float inv = 0.0078125f;
    #pragma unroll
    for (int mf = 0; mf < 2; mf++) {
        #pragma unroll
        for (int hsel = 0; hsel < 2; hsel++) {
            int m = warp_m + mf * 16 + (lane >> 2) + hsel * 8;
            int p = m_base + m;
            int ni = p / PIX; int rem = p - ni * PIX;
            int h = rem / WW; int w = rem - h * WW;
            float* op = out + (size_t)ni * CO * PIX + h * WW + w;
            #pragma unroll
            for (int nf = 0; nf < 8; nf++) {
                int col = warp_n + nf * 8 + 2 * (lane & 3);
                int co  = co_base + col;
                op[(size_t)co * PIX]       = acc[mf][nf][hsel*2 + 0] * inv + bq[col];
                op[(size_t)(co + 1) * PIX] = acc[mf][nf][hsel*2 + 1] * inv + bq[col + 1];
            }
        }
    }
}

// ---------------- launch ----------------
extern "C" void kernel_launch(void* const* d_in, const int* in_sizes, int n_in,
                              void* d_out, int out_size) {
    const float* x = (const float*)d_in[0];
    const float* W = (const float*)d_in[1];
    const float* b = (const float*)d_in[2];
    float* out = (float*)d_out;

    prep<<<TBLK + HBLK + WBLK, 256>>>(x, W);

    cudaFuncSetAttribute(qconv_gemm, cudaFuncAttributeMaxDynamicSharedMemorySize, SMEM_DYN);
    qconv_gemm<<<dim3(MTOT / 128, CO / 128), 256, SMEM_DYN>>>(b, out);
}